// round 16
// baseline (speedup 1.0000x reference)
#include <cuda_runtime.h>
#include <cuda_fp16.h>
#include <cstdint>
#include <cstdio>

// Shapes (fixed per problem)
#define Bb 4
#define Tt 2048
#define Ee 1024
#define Hh 16
#define Dh 64
#define Ff 4096
#define BT (Bb*Tt)          // 8192
#define E3 (3*Ee)           // 3072

// ---------------- scratch (static device memory; no allocations allowed) ----
__device__ __half g_wqkvT[(size_t)E3 * Ee];    // 6  MB  [3E, E] K-major
__device__ __half g_woT  [(size_t)Ee * Ee];    // 2  MB  [E, E]
__device__ __half g_w1T  [(size_t)Ff * Ee];    // 8  MB  [F, E]
__device__ __half g_w2T  [(size_t)Ee * Ff];    // 8  MB  [E, F]
__device__ __half g_h    [(size_t)BT * Ee];    // 16 MB  LN output
__device__ __half g_qkv  [(size_t)BT * E3];    // 48 MB  q|k|v
__device__ __half g_ctx  [(size_t)BT * Ee];    // 16 MB  attention out
__device__ float  g_x1   [(size_t)BT * Ee];    // 32 MB  x + attn residual (fp32)
__device__ __half g_a1   [(size_t)BT * Ff];    // 64 MB  relu(h2 W1 + b1)

// ---------------- helpers ----------------------------------------------------
__device__ __forceinline__ void cp16(uint32_t s, const void* g) {
    asm volatile("cp.async.cg.shared.global [%0], [%1], 16;" :: "r"(s), "l"(g) : "memory");
}
__device__ __forceinline__ uint32_t smem_u32(const void* p) {
    uint32_t a;
    asm("{ .reg .u64 t; cvta.to.shared.u64 t, %1; cvt.u32.u64 %0, t; }" : "=r"(a) : "l"(p));
    return a;
}
__device__ __forceinline__ void mma_f16(float c[4], const uint32_t a[4],
                                        uint32_t b0, uint32_t b1) {
    asm volatile(
        "mma.sync.aligned.m16n8k16.row.col.f32.f16.f16.f32 "
        "{%0,%1,%2,%3}, {%4,%5,%6,%7}, {%8,%9}, {%0,%1,%2,%3};"
        : "+f"(c[0]), "+f"(c[1]), "+f"(c[2]), "+f"(c[3])
        : "r"(a[0]), "r"(a[1]), "r"(a[2]), "r"(a[3]), "r"(b0), "r"(b1));
}
__device__ __forceinline__ void ldsm4(uint32_t r[4], uint32_t addr) {
    asm volatile("ldmatrix.sync.aligned.m8n8.x4.shared.b16 {%0,%1,%2,%3}, [%4];"
        : "=r"(r[0]), "=r"(r[1]), "=r"(r[2]), "=r"(r[3]) : "r"(addr));
}
__device__ __forceinline__ void ldsm4t(uint32_t r[4], uint32_t addr) {
    asm volatile("ldmatrix.sync.aligned.m8n8.x4.trans.shared.b16 {%0,%1,%2,%3}, [%4];"
        : "=r"(r[0]), "=r"(r[1]), "=r"(r[2]), "=r"(r[3]) : "r"(addr));
}

// =================== shared LN body ==========================================
__device__ __forceinline__ float blockReduceSum(float v)
{
    __shared__ float sh[8];
    __shared__ float tot;
    int lane = threadIdx.x & 31, w = threadIdx.x >> 5;
    #pragma unroll
    for (int o = 16; o > 0; o >>= 1) v += __shfl_xor_sync(0xffffffffu, v, o);
    if (lane == 0) sh[w] = v;
    __syncthreads();
    if (threadIdx.x < 32) {
        float t = (threadIdx.x < 8) ? sh[threadIdx.x] : 0.f;
        #pragma unroll
        for (int o = 4; o > 0; o >>= 1) t += __shfl_xor_sync(0xffffffffu, t, o);
        if (threadIdx.x == 0) tot = t;
    }
    __syncthreads();
    return tot;
}

__device__ __forceinline__ void ln_body(const float* __restrict__ x,
                                        const float* __restrict__ g,
                                        const float* __restrict__ beta,
                                        __half* __restrict__ out, int row)
{
    int tid = threadIdx.x;
    const float4* xr = (const float4*)(x + (size_t)row * Ee);
    float4 v = xr[tid];
    float s = v.x + v.y + v.z + v.w;
    s = blockReduceSum(s);
    float mu = s * (1.0f / Ee);
    float d0 = v.x - mu, d1 = v.y - mu, d2 = v.z - mu, d3 = v.w - mu;
    float ss = d0*d0 + d1*d1 + d2*d2 + d3*d3;
    ss = blockReduceSum(ss);
    float rstd = rsqrtf(ss * (1.0f / Ee) + 1e-5f);
    float4 gv = ((const float4*)g)[tid];
    float4 bv = ((const float4*)beta)[tid];
    __half2 h0 = __floats2half2_rn(d0 * rstd * gv.x + bv.x, d1 * rstd * gv.y + bv.y);
    __half2 h1 = __floats2half2_rn(d2 * rstd * gv.z + bv.z, d3 * rstd * gv.w + bv.w);
    __half2* o = (__half2*)(out + (size_t)row * Ee) + tid * 2;
    o[0] = h0;
    o[1] = h1;
}

__global__ __launch_bounds__(256)
void ln_kernel(const float* __restrict__ x, const float* __restrict__ g,
               const float* __restrict__ beta, __half* __restrict__ out)
{
    ln_body(x, g, beta, out, blockIdx.x);
}

// =================== fused prep: weight transposes + LN1 =====================
__device__ __forceinline__ void trans64x32(const float* __restrict__ in,
                                           __half* __restrict__ out,
                                           int Ns, int Ko, int kb, int nb)
{
    __shared__ float tile[64][33];
    int tid = threadIdx.x;
    int tx = tid & 31, ty = tid >> 5;
    #pragma unroll
    for (int r = 0; r < 8; r++)
        tile[ty + r * 8][tx] = in[(size_t)(kb + ty + r * 8) * Ns + nb + tx];
    __syncthreads();
    #pragma unroll
    for (int it = 0; it < 4; it++) {
        int n = ty + it * 8;
        __half2 v = __floats2half2_rn(tile[2 * tx][n], tile[2 * tx + 1][n]);
        *(__half2*)(out + (size_t)(nb + n) * Ko + kb + 2 * tx) = v;
    }
}

#define PREP_BLOCKS (BT + 512 + 2048 + 2048 + 1536)

__global__ __launch_bounds__(256)
void prep_kernel(const float* __restrict__ x, const float* __restrict__ g1,
                 const float* __restrict__ bt1, __half* __restrict__ hout,
                 const float* __restrict__ Wq, const float* __restrict__ Wk,
                 const float* __restrict__ Wv, __half* __restrict__ wqkvT,
                 const float* __restrict__ Wo, __half* __restrict__ woT,
                 const float* __restrict__ W1, __half* __restrict__ w1T,
                 const float* __restrict__ W2, __half* __restrict__ w2T)
{
    int bid = blockIdx.x;
    if (bid < BT) { ln_body(x, g1, bt1, hout, bid); return; }
    bid -= BT;
    if (bid < 512) {
        trans64x32(Wo, woT, Ee, Ee, (bid & 15) * 64, (bid >> 4) * 32);
        return;
    }
    bid -= 512;
    if (bid < 2048) {
        trans64x32(W1, w1T, Ff, Ee, (bid & 15) * 64, (bid >> 4) * 32);
        return;
    }
    bid -= 2048;
    if (bid < 2048) {
        trans64x32(W2, w2T, Ee, Ff, (bid & 63) * 64, (bid >> 6) * 32);
        return;
    }
    bid -= 2048;
    int wh = bid >> 5, inner = bid & 31;
    int which = wh >> 4, h = wh & 15;
    const float* W = (which == 0) ? Wq : (which == 1) ? Wk : Wv;
    trans64x32(W + (size_t)h * Ee * Dh,
               wqkvT + (size_t)(which * 1024 + h * 64) * Ee,
               Dh, Ee, (inner & 15) * 64, (inner >> 4) * 32);
}

// =================== fp16 mma.sync GEMM (persistent CTAs) ====================
#define BM 128
#define BN 128
#define BK 64
#define NST 3
#define STB (256*144)                 // 36864 bytes per stage
#define SMEM_G (NST * STB)            // 110592 bytes

template<bool RELU, bool BIAS, bool RES, bool HOUT>
__global__ __launch_bounds__(128, 2)
void gemm_mma(const __half* __restrict__ A, const __half* __restrict__ Bt,
              const float* __restrict__ bias, const float* __restrict__ res,
              void* __restrict__ Cv, int M, int N, int K)
{
    extern __shared__ char smc[];
    const uint32_t sb = smem_u32(smc);
    const int tid = threadIdx.x;
    const int wid = tid >> 5, lane = tid & 31;
    const int g = lane >> 2, t = lane & 3;
    const int wm = (wid >> 1) * 64, wn = (wid & 1) * 64;
    const int nK = K / BK;
    const int nx = N / BN;
    const int ntiles = (M / BM) * nx;

    const uint32_t laneA = (uint32_t)(wm + (lane & 15)) * 144u + ((lane & 16) ? 16u : 0u);
    const uint32_t laneB = (uint32_t)(wn + (lane & 7) + ((lane & 16) ? 8u : 0u)) * 144u
                           + ((lane & 8) ? 16u : 0u);

    for (int tile = blockIdx.x; tile < ntiles; tile += gridDim.x) {
        const int bm = (tile / nx) * BM, bn = (tile % nx) * BN;

        float acc[4][8][4];
        #pragma unroll
        for (int mi = 0; mi < 4; mi++)
            #pragma unroll
            for (int ni = 0; ni < 8; ni++)
                #pragma unroll
                for (int c = 0; c < 4; c++) acc[mi][ni][c] = 0.f;

        auto load_stage = [&](int s, int k0) {
            uint32_t sA = sb + (uint32_t)s * STB;
            uint32_t sB = sA + 128u * 144u;
            #pragma unroll
            for (int j = 0; j < 8; j++) {
                int idx = j * 128 + tid;
                int r = idx >> 3, c = idx & 7;
                cp16(sA + r * 144 + c * 16, A + (size_t)(bm + r) * K + k0 + c * 8);
                cp16(sB + r * 144 + c * 16, Bt + (size_t)(bn + r) * K + k0 + c * 8);
            }
        };

        load_stage(0, 0);
        asm volatile("cp.async.commit_group;" ::: "memory");
        load_stage(1, BK);
        asm volatile("cp.async.commit_group;" ::: "memory");

        uint32_t af[2][4][4], bf[2][4][4];

        for (int i = 0; i < nK; i++) {
            asm volatile("cp.async.wait_group 1;" ::: "memory");
            __syncthreads();
            int j = i + NST - 1;
            if (j < nK) load_stage(j % NST, j * BK);
            asm volatile("cp.async.commit_group;" ::: "memory");

            uint32_t abase = sb + (uint32_t)(i % NST) * STB + laneA;
            uint32_t bbase = sb + (uint32_t)(i % NST) * STB + 128u * 144u + laneB;

            #pragma unroll
            for (int mi = 0; mi < 4; mi++)
                ldsm4(af[0][mi], abase + (uint32_t)(mi * 16) * 144u);
            #pragma unroll
            for (int p = 0; p < 4; p++)
                ldsm4(bf[0][p], bbase + (uint32_t)(p * 16) * 144u);

            #pragma unroll
            for (int ks = 0; ks < 4; ks++) {
                int cur = ks & 1, nxt = cur ^ 1;
                if (ks < 3) {
                    uint32_t koff = (ks + 1) * 32;
                    #pragma unroll
                    for (int mi = 0; mi < 4; mi++)
                        ldsm4(af[nxt][mi], abase + (uint32_t)(mi * 16) * 144u + koff);
                    #pragma unroll
                    for (int p = 0; p < 4; p++)
                        ldsm4(bf[nxt][p], bbase + (uint32_t)(p * 16) * 144u + koff);
                }
                #pragma unroll
                for (int mi = 0; mi < 4; mi++) {
                    #pragma unroll
                    for (int p = 0; p < 4; p++) {
                        mma_f16(acc[mi][2*p],   af[cur][mi], bf[cur][p][0], bf[cur][p][1]);
                        mma_f16(acc[mi][2*p+1], af[cur][mi], bf[cur][p][2], bf[cur][p][3]);
                    }
                }
            }
        }

        #pragma unroll
        for (int ni = 0; ni < 8; ni++) {
            int col = bn + wn + ni * 8 + t * 2;
            float b0 = 0.f, b1 = 0.f;
            if (BIAS) {
                float2 bb = *(const float2*)(bias + col);
                b0 = bb.x; b1 = bb.y;
            }
            #pragma unroll
            for (int mi = 0; mi < 4; mi++) {
                int row0 = bm + wm + mi * 16 + g;
                #pragma unroll
                for (int h = 0; h < 2; h++) {
                    int row = row0 + h * 8;
                    float v0 = acc[mi][ni][h * 2 + 0] + b0;
                    float v1 = acc[mi][ni][h * 2 + 1] + b1;
                    if (RELU) { v0 = fmaxf(v0, 0.f); v1 = fmaxf(v1, 0.f); }
                    if (RES) {
                        float2 r2 = *(const float2*)(res + (size_t)row * N + col);
                        v0 += r2.x; v1 += r2.y;
                    }
                    if (HOUT) {
                        *(__half2*)((__half*)Cv + (size_t)row * N + col) =
                            __floats2half2_rn(v0, v1);
                    } else {
                        float2 o2; o2.x = v0; o2.y = v1;
                        *(float2*)((float*)Cv + (size_t)row * N + col) = o2;
                    }
                }
            }
        }

        // retire outstanding (empty) cp.async groups and make smem safe to reuse
        asm volatile("cp.async.wait_group 0;" ::: "memory");
        __syncthreads();
    }
}

// =================== fp16 tensor-core causal flash attention =================
#define APW 72
#define ATILE (64*APW*2)                    // 9216 bytes per tile
#define ATQ 0
#define ATK0 ATILE                          // 9216
#define ATV0 (3*ATILE)                      // 27648
#define ATP  (5*ATILE)                      // 46080
#define ATT_SMEM (6*ATILE)                  // 55296 bytes

__global__ __launch_bounds__(128)
void attn_tc(const __half* __restrict__ qkv, __half* __restrict__ ctx)
{
    extern __shared__ char smc[];
    const uint32_t sb = smem_u32(smc);
    int b = blockIdx.z, h = blockIdx.y;
    int qt0 = ((int)gridDim.x - 1 - (int)blockIdx.x) * 64;   // heavy blocks first
    int tid = threadIdx.x, wid = tid >> 5, lane = tid & 31;
    int g = lane >> 2, t = lane & 3;

    const __half* qbase = qkv + ((size_t)(b * Tt) + qt0) * E3 + h * Dh;
    const __half* kbase = qkv + (size_t)(b * Tt) * E3 + Ee + h * Dh;
    const __half* vbase = kbase + Ee;

    #pragma unroll
    for (int i2 = 0; i2 < 4; i2++) {
        int idx = i2 * 128 + tid;
        int r = idx >> 3, c = idx & 7;
        cp16(sb + ATQ + r * 144 + c * 16, qbase + (size_t)r * E3 + c * 8);
    }
    asm volatile("cp.async.commit_group;" ::: "memory");

    auto load_kv = [&](int tile, int buf) {
        int s0 = tile * 64;
        #pragma unroll
        for (int i2 = 0; i2 < 4; i2++) {
            int idx = i2 * 128 + tid;
            int r = idx >> 3, c = idx & 7;
            cp16(sb + ATK0 + buf * ATILE + r * 144 + c * 16,
                 kbase + (size_t)(s0 + r) * E3 + c * 8);
            cp16(sb + ATV0 + buf * ATILE + r * 144 + c * 16,
                 vbase + (size_t)(s0 + r) * E3 + c * 8);
        }
        asm volatile("cp.async.commit_group;" ::: "memory");
    };

    int ntiles = qt0 / 64 + 1;
    load_kv(0, 0);
    asm volatile("cp.async.wait_group 0;" ::: "memory");
    __syncthreads();

    const uint32_t laneQ = (uint32_t)(wid * 16 + (lane & 15)) * 144u + ((lane & 16) ? 16u : 0u);
    const uint32_t laneK = (uint32_t)((lane & 7) + ((lane & 16) ? 8u : 0u)) * 144u
                           + ((lane & 8) ? 16u : 0u);
    const uint32_t laneP = (uint32_t)(lane & 15) * 144u + ((lane & 16) ? 16u : 0u);
    const uint32_t laneV = (uint32_t)((lane & 7) + ((lane & 8) ? 8u : 0u)) * 144u
                           + ((lane & 16) ? 16u : 0u);

    uint32_t af[4][4];
    #pragma unroll
    for (int ks = 0; ks < 4; ks++)
        ldsm4(af[ks], sb + ATQ + laneQ + ks * 32);

    float acc[8][4];
    #pragma unroll
    for (int ni = 0; ni < 8; ni++)
        #pragma unroll
        for (int c = 0; c < 4; c++) acc[ni][c] = 0.f;
    float m0 = -1e30f, m1 = -1e30f, l0 = 0.f, l1 = 0.f;

    const uint32_t pwarp = ATP + (uint32_t)(wid * 16) * 144u;

    for (int i = 0; i < ntiles; i++) {
        if (i + 1 < ntiles) load_kv(i + 1, (i + 1) & 1);

        uint32_t skb = sb + ATK0 + (uint32_t)(i & 1) * ATILE;
        uint32_t svb = sb + ATV0 + (uint32_t)(i & 1) * ATILE;

        float s[8][4];
        #pragma unroll
        for (int ni = 0; ni < 8; ni++)
            s[ni][0] = s[ni][1] = s[ni][2] = s[ni][3] = 0.f;
        #pragma unroll
        for (int ks = 0; ks < 4; ks++) {
            uint32_t kf[4][4];
            #pragma unroll
            for (int nb = 0; nb < 4; nb++)
                ldsm4(kf[nb], skb + laneK + (uint32_t)(nb * 16) * 144u + ks * 32);
            #pragma unroll
            for (int nb = 0; nb < 4; nb++) {
                mma_f16(s[2*nb],   af[ks], kf[nb][0], kf[nb][1]);
                mma_f16(s[2*nb+1], af[ks], kf[nb][2], kf[nb][3]);
            }
        }

        bool diag = (i == ntiles - 1);
        float rm0 = -1e30f, rm1 = -1e30f;
        #pragma unroll
        for (int ni = 0; ni < 8; ni++) {
            float v0 = s[ni][0] * 0.03125f;
            float v1 = s[ni][1] * 0.03125f;
            float v2 = s[ni][2] * 0.03125f;
            float v3 = s[ni][3] * 0.03125f;
            if (diag) {
                int colk = ni * 8 + 2 * t;
                int r0 = wid * 16 + g, r1 = r0 + 8;
                if (colk     > r0) v0 = -1e30f;
                if (colk + 1 > r0) v1 = -1e30f;
                if (colk     > r1) v2 = -1e30f;
                if (colk + 1 > r1) v3 = -1e30f;
            }
            s[ni][0] = v0; s[ni][1] = v1; s[ni][2] = v2; s[ni][3] = v3;
            rm0 = fmaxf(rm0, fmaxf(v0, v1));
            rm1 = fmaxf(rm1, fmaxf(v2, v3));
        }
        rm0 = fmaxf(rm0, __shfl_xor_sync(0xffffffffu, rm0, 1));
        rm0 = fmaxf(rm0, __shfl_xor_sync(0xffffffffu, rm0, 2));
        rm1 = fmaxf(rm1, __shfl_xor_sync(0xffffffffu, rm1, 1));
        rm1 = fmaxf(rm1, __shfl_xor_sync(0xffffffffu, rm1, 2));

        float mn0 = fmaxf(m0, rm0), mn1 = fmaxf(m1, rm1);
        float corr0 = __expf(m0 - mn0), corr1 = __expf(m1 - mn1);
        m0 = mn0; m1 = mn1;
        l0 *= corr0; l1 *= corr1;

        #pragma unroll
        for (int ni = 0; ni < 8; ni++) {
            float p0 = __expf(s[ni][0] - m0);
            float p1 = __expf(s[ni][1] - m0);
            float p2 = __expf(s[ni][2] - m1);
            float p3 = __expf(s[ni][3] - m1);
            l0 += p0 + p1;
            l1 += p2 + p3;
            acc[ni][0] *= corr0; acc[ni][1] *= corr0;
            acc[ni][2] *= corr1; acc[ni][3] *= corr1;
            *(__half2*)(smc + pwarp + g * 144 + (ni * 8 + 2 * t) * 2) =
                __floats2half2_rn(p0, p1);
            *(__half2*)(smc + pwarp + (g + 8) * 144 + (ni * 8 + 2 * t) * 2) =
                __floats2half2_rn(p2, p3);
        }
        __syncwarp();

        uint32_t pf[4][4];
        #pragma unroll
        for (int ks = 0; ks < 4; ks++)
            ldsm4(pf[ks], sb + pwarp + laneP + ks * 32);

        #pragma unroll
        for (int ks = 0; ks < 4; ks++) {
            uint32_t vf[4][4];
            #pragma unroll
            for (int nb = 0; nb < 4; nb++)
                ldsm4t(vf[nb], svb + laneV + (uint32_t)(ks * 16) * 144u + nb * 32);
            #pragma unroll
            for (int nb = 0; nb < 4; nb++) {
                mma_f16(acc[2*nb],   pf[ks], vf[nb][0], vf[nb][1]);
                mma_f16(acc[2*nb+1], pf[ks], vf[nb][2], vf[nb][3]);
            }
        }

        if (i + 1 < ntiles) {
            asm volatile("cp.async.wait_group 0;" ::: "memory");
            __syncthreads();
        }
    }

    l0 += __shfl_xor_sync(0xffffffffu, l0, 1);
    l0 += __shfl_xor_sync(0xffffffffu, l0, 2);
    l1 += __shfl_xor_sync(0xffffffffu, l1, 1);
    l1 += __shfl_xor_sync(0xffffffffu, l1, 2);
    float inv0 = 1.0f / l0, inv1 = 1.0f / l1;

    int row0 = qt0 + wid * 16 + g;
    __half* ob = ctx + (size_t)(b * Tt) * Ee + h * Dh;
    #pragma unroll
    for (int ni = 0; ni < 8; ni++) {
        int d = ni * 8 + 2 * t;
        *(__half2*)(ob + (size_t)row0 * Ee + d) =
            __floats2half2_rn(acc[ni][0] * inv0, acc[ni][1] * inv0);
        *(__half2*)(ob + (size_t)(row0 + 8) * Ee + d) =
            __floats2half2_rn(acc[ni][2] * inv1, acc[ni][3] * inv1);
    }
}

// =================== launch ==================================================
extern "C" void kernel_launch(void* const* d_in, const int* in_sizes, int n_in,
                              void* d_out, int out_size)
{
    const float* x   = (const float*)d_in[0];
    const float* Wq  = (const float*)d_in[1];
    const float* Wk  = (const float*)d_in[2];
    const float* Wv  = (const float*)d_in[3];
    const float* Wo  = (const float*)d_in[4];
    const float* bo  = (const float*)d_in[5];
    const float* W1  = (const float*)d_in[6];
    const float* b1  = (const float*)d_in[7];
    const float* W2  = (const float*)d_in[8];
    const float* b2  = (const float*)d_in[9];
    const float* g1  = (const float*)d_in[10];
    const float* bt1 = (const float*)d_in[11];
    const float* g2  = (const float*)d_in[12];
    const float* bt2 = (const float*)d_in[13];
    float* out = (float*)d_out;

    __half *p_wqkvT, *p_woT, *p_w1T, *p_w2T, *p_h, *p_qkv, *p_ctx, *p_a1;
    float *p_x1;
    cudaGetSymbolAddress((void**)&p_wqkvT, g_wqkvT);
    cudaGetSymbolAddress((void**)&p_woT,   g_woT);
    cudaGetSymbolAddress((void**)&p_w1T,   g_w1T);
    cudaGetSymbolAddress((void**)&p_w2T,   g_w2T);
    cudaGetSymbolAddress((void**)&p_h,     g_h);
    cudaGetSymbolAddress((void**)&p_qkv,   g_qkv);
    cudaGetSymbolAddress((void**)&p_ctx,   g_ctx);
    cudaGetSymbolAddress((void**)&p_x1,    g_x1);
    cudaGetSymbolAddress((void**)&p_a1,    g_a1);

    int nsm = 148;
    cudaDeviceGetAttribute(&nsm, cudaDevAttrMultiProcessorCount, 0);
    int pgrid = nsm * 2;                      // exactly-resident persistent grid

    cudaFuncSetAttribute(gemm_mma<false,false,false,true>,
                         cudaFuncAttributeMaxDynamicSharedMemorySize, SMEM_G);
    cudaFuncSetAttribute(gemm_mma<false,true,true,false>,
                         cudaFuncAttributeMaxDynamicSharedMemorySize, SMEM_G);
    cudaFuncSetAttribute(gemm_mma<true,true,false,true>,
                         cudaFuncAttributeMaxDynamicSharedMemorySize, SMEM_G);
    cudaFuncSetAttribute(attn_tc,
                         cudaFuncAttributeMaxDynamicSharedMemorySize, ATT_SMEM);

    // 1. fused prep: LN1 + all weight transposes (one launch)
    prep_kernel<<<PREP_BLOCKS, 256>>>(x, g1, bt1, p_h,
                                      Wq, Wk, Wv, p_wqkvT,
                                      Wo, p_woT, W1, p_w1T, W2, p_w2T);
    // 2. qkv = h @ Wqkv  (fp16 out)
    gemm_mma<false,false,false,true><<<pgrid, 128, SMEM_G>>>(
        p_h, p_wqkvT, nullptr, nullptr, p_qkv, BT, E3, Ee);
    // 3. ctx = causal attention (fp16 tensor core)
    attn_tc<<<dim3(Tt/64, Hh, Bb), 128, ATT_SMEM>>>(p_qkv, p_ctx);
    // 4. x1 = x + ctx @ Wo + bo  (fp32 out)
    gemm_mma<false,true,true,false><<<pgrid, 128, SMEM_G>>>(
        p_ctx, p_woT, bo, x, p_x1, BT, Ee, Ee);
    // 5. h2 = LN(x1)  (fp16)
    ln_kernel<<<BT, 256>>>(p_x1, g2, bt2, p_h);
    // 6. a1 = relu(h2 @ W1 + b1)  (fp16 out)
    gemm_mma<true,true,false,true><<<pgrid, 128, SMEM_G>>>(
        p_h, p_w1T, b1, nullptr, p_a1, BT, Ff, Ee);
    // 7. out = x1 + a1 @ W2 + b2  (fp32 out)
    gemm_mma<false,true,true,false><<<pgrid, 128, SMEM_G>>>(
        p_a1, p_w2T, b2, p_x1, out, BT, Ee, Ff);
}

// round 17
// speedup vs baseline: 1.0370x; 1.0370x over previous
#include <cuda_runtime.h>
#include <cuda_fp16.h>
#include <cstdint>
#include <cstdio>

// Shapes (fixed per problem)
#define Bb 4
#define Tt 2048
#define Ee 1024
#define Hh 16
#define Dh 64
#define Ff 4096
#define BT (Bb*Tt)          // 8192
#define E3 (3*Ee)           // 3072

// ---------------- scratch (static device memory; no allocations allowed) ----
__device__ __half g_wqkvT[(size_t)E3 * Ee];    // 6  MB  [3E, E] K-major
__device__ __half g_woT  [(size_t)Ee * Ee];    // 2  MB  [E, E]
__device__ __half g_w1T  [(size_t)Ff * Ee];    // 8  MB  [F, E]
__device__ __half g_w2T  [(size_t)Ee * Ff];    // 8  MB  [E, F]
__device__ __half g_h    [(size_t)BT * Ee];    // 16 MB  LN output
__device__ __half g_qkv  [(size_t)BT * E3];    // 48 MB  q|k|v
__device__ __half g_ctx  [(size_t)BT * Ee];    // 16 MB  attention out
__device__ float  g_x1   [(size_t)BT * Ee];    // 32 MB  x + attn residual (fp32)
__device__ __half g_a1   [(size_t)BT * Ff];    // 64 MB  relu(h2 W1 + b1)

// ---------------- helpers ----------------------------------------------------
__device__ __forceinline__ void cp16(uint32_t s, const void* g) {
    asm volatile("cp.async.cg.shared.global [%0], [%1], 16;" :: "r"(s), "l"(g) : "memory");
}
__device__ __forceinline__ uint32_t smem_u32(const void* p) {
    uint32_t a;
    asm("{ .reg .u64 t; cvta.to.shared.u64 t, %1; cvt.u32.u64 %0, t; }" : "=r"(a) : "l"(p));
    return a;
}
__device__ __forceinline__ void mma_f16(float c[4], const uint32_t a[4],
                                        uint32_t b0, uint32_t b1) {
    asm volatile(
        "mma.sync.aligned.m16n8k16.row.col.f32.f16.f16.f32 "
        "{%0,%1,%2,%3}, {%4,%5,%6,%7}, {%8,%9}, {%0,%1,%2,%3};"
        : "+f"(c[0]), "+f"(c[1]), "+f"(c[2]), "+f"(c[3])
        : "r"(a[0]), "r"(a[1]), "r"(a[2]), "r"(a[3]), "r"(b0), "r"(b1));
}
__device__ __forceinline__ void ldsm4(uint32_t r[4], uint32_t addr) {
    asm volatile("ldmatrix.sync.aligned.m8n8.x4.shared.b16 {%0,%1,%2,%3}, [%4];"
        : "=r"(r[0]), "=r"(r[1]), "=r"(r[2]), "=r"(r[3]) : "r"(addr));
}
__device__ __forceinline__ void ldsm4t(uint32_t r[4], uint32_t addr) {
    asm volatile("ldmatrix.sync.aligned.m8n8.x4.trans.shared.b16 {%0,%1,%2,%3}, [%4];"
        : "=r"(r[0]), "=r"(r[1]), "=r"(r[2]), "=r"(r[3]) : "r"(addr));
}

// =================== shared LN body ==========================================
__device__ __forceinline__ float blockReduceSum(float v)
{
    __shared__ float sh[8];
    __shared__ float tot;
    int lane = threadIdx.x & 31, w = threadIdx.x >> 5;
    #pragma unroll
    for (int o = 16; o > 0; o >>= 1) v += __shfl_xor_sync(0xffffffffu, v, o);
    if (lane == 0) sh[w] = v;
    __syncthreads();
    if (threadIdx.x < 32) {
        float t = (threadIdx.x < 8) ? sh[threadIdx.x] : 0.f;
        #pragma unroll
        for (int o = 4; o > 0; o >>= 1) t += __shfl_xor_sync(0xffffffffu, t, o);
        if (threadIdx.x == 0) tot = t;
    }
    __syncthreads();
    return tot;
}

__device__ __forceinline__ void ln_body(const float* __restrict__ x,
                                        const float* __restrict__ g,
                                        const float* __restrict__ beta,
                                        __half* __restrict__ out, int row)
{
    int tid = threadIdx.x;
    const float4* xr = (const float4*)(x + (size_t)row * Ee);
    float4 v = xr[tid];
    float s = v.x + v.y + v.z + v.w;
    s = blockReduceSum(s);
    float mu = s * (1.0f / Ee);
    float d0 = v.x - mu, d1 = v.y - mu, d2 = v.z - mu, d3 = v.w - mu;
    float ss = d0*d0 + d1*d1 + d2*d2 + d3*d3;
    ss = blockReduceSum(ss);
    float rstd = rsqrtf(ss * (1.0f / Ee) + 1e-5f);
    float4 gv = ((const float4*)g)[tid];
    float4 bv = ((const float4*)beta)[tid];
    __half2 h0 = __floats2half2_rn(d0 * rstd * gv.x + bv.x, d1 * rstd * gv.y + bv.y);
    __half2 h1 = __floats2half2_rn(d2 * rstd * gv.z + bv.z, d3 * rstd * gv.w + bv.w);
    __half2* o = (__half2*)(out + (size_t)row * Ee) + tid * 2;
    o[0] = h0;
    o[1] = h1;
}

__global__ __launch_bounds__(256)
void ln_kernel(const float* __restrict__ x, const float* __restrict__ g,
               const float* __restrict__ beta, __half* __restrict__ out)
{
    ln_body(x, g, beta, out, blockIdx.x);
}

// =================== fused prep: weight transposes + LN1 =====================
__device__ __forceinline__ void trans64x32(const float* __restrict__ in,
                                           __half* __restrict__ out,
                                           int Ns, int Ko, int kb, int nb)
{
    __shared__ float tile[64][33];
    int tid = threadIdx.x;
    int tx = tid & 31, ty = tid >> 5;
    #pragma unroll
    for (int r = 0; r < 8; r++)
        tile[ty + r * 8][tx] = in[(size_t)(kb + ty + r * 8) * Ns + nb + tx];
    __syncthreads();
    #pragma unroll
    for (int it = 0; it < 4; it++) {
        int n = ty + it * 8;
        __half2 v = __floats2half2_rn(tile[2 * tx][n], tile[2 * tx + 1][n]);
        *(__half2*)(out + (size_t)(nb + n) * Ko + kb + 2 * tx) = v;
    }
}

#define PREP_BLOCKS (BT + 512 + 2048 + 2048 + 1536)

__global__ __launch_bounds__(256)
void prep_kernel(const float* __restrict__ x, const float* __restrict__ g1,
                 const float* __restrict__ bt1, __half* __restrict__ hout,
                 const float* __restrict__ Wq, const float* __restrict__ Wk,
                 const float* __restrict__ Wv, __half* __restrict__ wqkvT,
                 const float* __restrict__ Wo, __half* __restrict__ woT,
                 const float* __restrict__ W1, __half* __restrict__ w1T,
                 const float* __restrict__ W2, __half* __restrict__ w2T)
{
    int bid = blockIdx.x;
    if (bid < BT) { ln_body(x, g1, bt1, hout, bid); return; }
    bid -= BT;
    if (bid < 512) {
        trans64x32(Wo, woT, Ee, Ee, (bid & 15) * 64, (bid >> 4) * 32);
        return;
    }
    bid -= 512;
    if (bid < 2048) {
        trans64x32(W1, w1T, Ff, Ee, (bid & 15) * 64, (bid >> 4) * 32);
        return;
    }
    bid -= 2048;
    if (bid < 2048) {
        trans64x32(W2, w2T, Ee, Ff, (bid & 63) * 64, (bid >> 6) * 32);
        return;
    }
    bid -= 2048;
    int wh = bid >> 5, inner = bid & 31;
    int which = wh >> 4, h = wh & 15;
    const float* W = (which == 0) ? Wq : (which == 1) ? Wk : Wv;
    trans64x32(W + (size_t)h * Ee * Dh,
               wqkvT + (size_t)(which * 1024 + h * 64) * Ee,
               Dh, Ee, (inner & 15) * 64, (inner >> 4) * 32);
}

// =================== fp16 mma.sync GEMM (R15 proven config) ==================
#define BM 128
#define BN 128
#define BK 64
#define NST 3
#define STB (256*144)                 // 36864 bytes per stage
#define SMEM_G (NST * STB)            // 110592 bytes

template<bool RELU, bool BIAS, bool RES, bool HOUT>
__global__ __launch_bounds__(128, 2)
void gemm_mma(const __half* __restrict__ A, const __half* __restrict__ Bt,
              const float* __restrict__ bias, const float* __restrict__ res,
              void* __restrict__ Cv, int M, int N, int K)
{
    extern __shared__ char smc[];
    const uint32_t sb = smem_u32(smc);
    const int tid = threadIdx.x;
    const int wid = tid >> 5, lane = tid & 31;
    const int g = lane >> 2, t = lane & 3;
    const int wm = (wid >> 1) * 64, wn = (wid & 1) * 64;
    const int bm = blockIdx.y * BM, bn = blockIdx.x * BN;
    const int nK = K / BK;

    const uint32_t laneA = (uint32_t)(wm + (lane & 15)) * 144u + ((lane & 16) ? 16u : 0u);
    const uint32_t laneB = (uint32_t)(wn + (lane & 7) + ((lane & 16) ? 8u : 0u)) * 144u
                           + ((lane & 8) ? 16u : 0u);

    float acc[4][8][4];
    #pragma unroll
    for (int mi = 0; mi < 4; mi++)
        #pragma unroll
        for (int ni = 0; ni < 8; ni++)
            #pragma unroll
            for (int c = 0; c < 4; c++) acc[mi][ni][c] = 0.f;

    auto load_stage = [&](int s, int k0) {
        uint32_t sA = sb + (uint32_t)s * STB;
        uint32_t sB = sA + 128u * 144u;
        #pragma unroll
        for (int j = 0; j < 8; j++) {
            int idx = j * 128 + tid;
            int r = idx >> 3, c = idx & 7;
            cp16(sA + r * 144 + c * 16, A + (size_t)(bm + r) * K + k0 + c * 8);
            cp16(sB + r * 144 + c * 16, Bt + (size_t)(bn + r) * K + k0 + c * 8);
        }
    };

    load_stage(0, 0);
    asm volatile("cp.async.commit_group;" ::: "memory");
    load_stage(1, BK);
    asm volatile("cp.async.commit_group;" ::: "memory");

    uint32_t af[2][4][4], bf[2][4][4];

    for (int i = 0; i < nK; i++) {
        asm volatile("cp.async.wait_group 1;" ::: "memory");
        __syncthreads();
        int j = i + NST - 1;
        if (j < nK) load_stage(j % NST, j * BK);
        asm volatile("cp.async.commit_group;" ::: "memory");

        uint32_t abase = sb + (uint32_t)(i % NST) * STB + laneA;
        uint32_t bbase = sb + (uint32_t)(i % NST) * STB + 128u * 144u + laneB;

        #pragma unroll
        for (int mi = 0; mi < 4; mi++)
            ldsm4(af[0][mi], abase + (uint32_t)(mi * 16) * 144u);
        #pragma unroll
        for (int p = 0; p < 4; p++)
            ldsm4(bf[0][p], bbase + (uint32_t)(p * 16) * 144u);

        #pragma unroll
        for (int ks = 0; ks < 4; ks++) {
            int cur = ks & 1, nxt = cur ^ 1;
            if (ks < 3) {
                uint32_t koff = (ks + 1) * 32;
                #pragma unroll
                for (int mi = 0; mi < 4; mi++)
                    ldsm4(af[nxt][mi], abase + (uint32_t)(mi * 16) * 144u + koff);
                #pragma unroll
                for (int p = 0; p < 4; p++)
                    ldsm4(bf[nxt][p], bbase + (uint32_t)(p * 16) * 144u + koff);
            }
            #pragma unroll
            for (int mi = 0; mi < 4; mi++) {
                #pragma unroll
                for (int p = 0; p < 4; p++) {
                    mma_f16(acc[mi][2*p],   af[cur][mi], bf[cur][p][0], bf[cur][p][1]);
                    mma_f16(acc[mi][2*p+1], af[cur][mi], bf[cur][p][2], bf[cur][p][3]);
                }
            }
        }
    }

    #pragma unroll
    for (int ni = 0; ni < 8; ni++) {
        int col = bn + wn + ni * 8 + t * 2;
        float b0 = 0.f, b1 = 0.f;
        if (BIAS) {
            float2 bb = *(const float2*)(bias + col);
            b0 = bb.x; b1 = bb.y;
        }
        #pragma unroll
        for (int mi = 0; mi < 4; mi++) {
            int row0 = bm + wm + mi * 16 + g;
            #pragma unroll
            for (int h = 0; h < 2; h++) {
                int row = row0 + h * 8;
                float v0 = acc[mi][ni][h * 2 + 0] + b0;
                float v1 = acc[mi][ni][h * 2 + 1] + b1;
                if (RELU) { v0 = fmaxf(v0, 0.f); v1 = fmaxf(v1, 0.f); }
                if (RES) {
                    float2 r2 = *(const float2*)(res + (size_t)row * N + col);
                    v0 += r2.x; v1 += r2.y;
                }
                if (HOUT) {
                    *(__half2*)((__half*)Cv + (size_t)row * N + col) =
                        __floats2half2_rn(v0, v1);
                } else {
                    float2 o2; o2.x = v0; o2.y = v1;
                    *(float2*)((float*)Cv + (size_t)row * N + col) = o2;
                }
            }
        }
    }
}

// =================== fp16 tensor-core causal flash attention =================
// Block: 64 queries x 1 head, 128 threads, forced 4 CTAs/SM residency.
#define APW 72
#define ATILE (64*APW*2)                    // 9216 bytes per tile
#define ATQ 0
#define ATK0 ATILE                          // 9216
#define ATV0 (3*ATILE)                      // 27648
#define ATP  (5*ATILE)                      // 46080
#define ATT_SMEM (6*ATILE)                  // 55296 bytes

__global__ __launch_bounds__(128, 4)
void attn_tc(const __half* __restrict__ qkv, __half* __restrict__ ctx)
{
    extern __shared__ char smc[];
    const uint32_t sb = smem_u32(smc);
    int b = blockIdx.z, h = blockIdx.y;
    int qt0 = ((int)gridDim.x - 1 - (int)blockIdx.x) * 64;   // heavy blocks first
    int tid = threadIdx.x, wid = tid >> 5, lane = tid & 31;
    int g = lane >> 2, t = lane & 3;

    const __half* qbase = qkv + ((size_t)(b * Tt) + qt0) * E3 + h * Dh;
    const __half* kbase = qkv + (size_t)(b * Tt) * E3 + Ee + h * Dh;
    const __half* vbase = kbase + Ee;

    #pragma unroll
    for (int i2 = 0; i2 < 4; i2++) {
        int idx = i2 * 128 + tid;
        int r = idx >> 3, c = idx & 7;
        cp16(sb + ATQ + r * 144 + c * 16, qbase + (size_t)r * E3 + c * 8);
    }
    asm volatile("cp.async.commit_group;" ::: "memory");

    auto load_kv = [&](int tile, int buf) {
        int s0 = tile * 64;
        #pragma unroll
        for (int i2 = 0; i2 < 4; i2++) {
            int idx = i2 * 128 + tid;
            int r = idx >> 3, c = idx & 7;
            cp16(sb + ATK0 + buf * ATILE + r * 144 + c * 16,
                 kbase + (size_t)(s0 + r) * E3 + c * 8);
            cp16(sb + ATV0 + buf * ATILE + r * 144 + c * 16,
                 vbase + (size_t)(s0 + r) * E3 + c * 8);
        }
        asm volatile("cp.async.commit_group;" ::: "memory");
    };

    int ntiles = qt0 / 64 + 1;
    load_kv(0, 0);
    asm volatile("cp.async.wait_group 0;" ::: "memory");
    __syncthreads();

    const uint32_t laneQ = (uint32_t)(wid * 16 + (lane & 15)) * 144u + ((lane & 16) ? 16u : 0u);
    const uint32_t laneK = (uint32_t)((lane & 7) + ((lane & 16) ? 8u : 0u)) * 144u
                           + ((lane & 8) ? 16u : 0u);
    const uint32_t laneP = (uint32_t)(lane & 15) * 144u + ((lane & 16) ? 16u : 0u);
    const uint32_t laneV = (uint32_t)((lane & 7) + ((lane & 8) ? 8u : 0u)) * 144u
                           + ((lane & 16) ? 16u : 0u);

    uint32_t af[4][4];
    #pragma unroll
    for (int ks = 0; ks < 4; ks++)
        ldsm4(af[ks], sb + ATQ + laneQ + ks * 32);

    float acc[8][4];
    #pragma unroll
    for (int ni = 0; ni < 8; ni++)
        #pragma unroll
        for (int c = 0; c < 4; c++) acc[ni][c] = 0.f;
    float m0 = -1e30f, m1 = -1e30f, l0 = 0.f, l1 = 0.f;

    const uint32_t pwarp = ATP + (uint32_t)(wid * 16) * 144u;

    for (int i = 0; i < ntiles; i++) {
        if (i + 1 < ntiles) load_kv(i + 1, (i + 1) & 1);

        uint32_t skb = sb + ATK0 + (uint32_t)(i & 1) * ATILE;
        uint32_t svb = sb + ATV0 + (uint32_t)(i & 1) * ATILE;

        float s[8][4];
        #pragma unroll
        for (int ni = 0; ni < 8; ni++)
            s[ni][0] = s[ni][1] = s[ni][2] = s[ni][3] = 0.f;
        #pragma unroll
        for (int ks = 0; ks < 4; ks++) {
            uint32_t kf[4][4];
            #pragma unroll
            for (int nb = 0; nb < 4; nb++)
                ldsm4(kf[nb], skb + laneK + (uint32_t)(nb * 16) * 144u + ks * 32);
            #pragma unroll
            for (int nb = 0; nb < 4; nb++) {
                mma_f16(s[2*nb],   af[ks], kf[nb][0], kf[nb][1]);
                mma_f16(s[2*nb+1], af[ks], kf[nb][2], kf[nb][3]);
            }
        }

        bool diag = (i == ntiles - 1);
        float rm0 = -1e30f, rm1 = -1e30f;
        #pragma unroll
        for (int ni = 0; ni < 8; ni++) {
            float v0 = s[ni][0] * 0.03125f;
            float v1 = s[ni][1] * 0.03125f;
            float v2 = s[ni][2] * 0.03125f;
            float v3 = s[ni][3] * 0.03125f;
            if (diag) {
                int colk = ni * 8 + 2 * t;
                int r0 = wid * 16 + g, r1 = r0 + 8;
                if (colk     > r0) v0 = -1e30f;
                if (colk + 1 > r0) v1 = -1e30f;
                if (colk     > r1) v2 = -1e30f;
                if (colk + 1 > r1) v3 = -1e30f;
            }
            s[ni][0] = v0; s[ni][1] = v1; s[ni][2] = v2; s[ni][3] = v3;
            rm0 = fmaxf(rm0, fmaxf(v0, v1));
            rm1 = fmaxf(rm1, fmaxf(v2, v3));
        }
        rm0 = fmaxf(rm0, __shfl_xor_sync(0xffffffffu, rm0, 1));
        rm0 = fmaxf(rm0, __shfl_xor_sync(0xffffffffu, rm0, 2));
        rm1 = fmaxf(rm1, __shfl_xor_sync(0xffffffffu, rm1, 1));
        rm1 = fmaxf(rm1, __shfl_xor_sync(0xffffffffu, rm1, 2));

        float mn0 = fmaxf(m0, rm0), mn1 = fmaxf(m1, rm1);
        float corr0 = __expf(m0 - mn0), corr1 = __expf(m1 - mn1);
        m0 = mn0; m1 = mn1;
        l0 *= corr0; l1 *= corr1;

        #pragma unroll
        for (int ni = 0; ni < 8; ni++) {
            float p0 = __expf(s[ni][0] - m0);
            float p1 = __expf(s[ni][1] - m0);
            float p2 = __expf(s[ni][2] - m1);
            float p3 = __expf(s[ni][3] - m1);
            l0 += p0 + p1;
            l1 += p2 + p3;
            acc[ni][0] *= corr0; acc[ni][1] *= corr0;
            acc[ni][2] *= corr1; acc[ni][3] *= corr1;
            *(__half2*)(smc + pwarp + g * 144 + (ni * 8 + 2 * t) * 2) =
                __floats2half2_rn(p0, p1);
            *(__half2*)(smc + pwarp + (g + 8) * 144 + (ni * 8 + 2 * t) * 2) =
                __floats2half2_rn(p2, p3);
        }
        __syncwarp();

        uint32_t pf[4][4];
        #pragma unroll
        for (int ks = 0; ks < 4; ks++)
            ldsm4(pf[ks], sb + pwarp + laneP + ks * 32);

        #pragma unroll
        for (int ks = 0; ks < 4; ks++) {
            uint32_t vf[4][4];
            #pragma unroll
            for (int nb = 0; nb < 4; nb++)
                ldsm4t(vf[nb], svb + laneV + (uint32_t)(ks * 16) * 144u + nb * 32);
            #pragma unroll
            for (int nb = 0; nb < 4; nb++) {
                mma_f16(acc[2*nb],   pf[ks], vf[nb][0], vf[nb][1]);
                mma_f16(acc[2*nb+1], pf[ks], vf[nb][2], vf[nb][3]);
            }
        }

        if (i + 1 < ntiles) {
            asm volatile("cp.async.wait_group 0;" ::: "memory");
            __syncthreads();
        }
    }

    l0 += __shfl_xor_sync(0xffffffffu, l0, 1);
    l0 += __shfl_xor_sync(0xffffffffu, l0, 2);
    l1 += __shfl_xor_sync(0xffffffffu, l1, 1);
    l1 += __shfl_xor_sync(0xffffffffu, l1, 2);
    float inv0 = 1.0f / l0, inv1 = 1.0f / l1;

    int row0 = qt0 + wid * 16 + g;
    __half* ob = ctx + (size_t)(b * Tt) * Ee + h * Dh;
    #pragma unroll
    for (int ni = 0; ni < 8; ni++) {
        int d = ni * 8 + 2 * t;
        *(__half2*)(ob + (size_t)row0 * Ee + d) =
            __floats2half2_rn(acc[ni][0] * inv0, acc[ni][1] * inv0);
        *(__half2*)(ob + (size_t)(row0 + 8) * Ee + d) =
            __floats2half2_rn(acc[ni][2] * inv1, acc[ni][3] * inv1);
    }
}

// =================== launch ==================================================
extern "C" void kernel_launch(void* const* d_in, const int* in_sizes, int n_in,
                              void* d_out, int out_size)
{
    const float* x   = (const float*)d_in[0];
    const float* Wq  = (const float*)d_in[1];
    const float* Wk  = (const float*)d_in[2];
    const float* Wv  = (const float*)d_in[3];
    const float* Wo  = (const float*)d_in[4];
    const float* bo  = (const float*)d_in[5];
    const float* W1  = (const float*)d_in[6];
    const float* b1  = (const float*)d_in[7];
    const float* W2  = (const float*)d_in[8];
    const float* b2  = (const float*)d_in[9];
    const float* g1  = (const float*)d_in[10];
    const float* bt1 = (const float*)d_in[11];
    const float* g2  = (const float*)d_in[12];
    const float* bt2 = (const float*)d_in[13];
    float* out = (float*)d_out;

    __half *p_wqkvT, *p_woT, *p_w1T, *p_w2T, *p_h, *p_qkv, *p_ctx, *p_a1;
    float *p_x1;
    cudaGetSymbolAddress((void**)&p_wqkvT, g_wqkvT);
    cudaGetSymbolAddress((void**)&p_woT,   g_woT);
    cudaGetSymbolAddress((void**)&p_w1T,   g_w1T);
    cudaGetSymbolAddress((void**)&p_w2T,   g_w2T);
    cudaGetSymbolAddress((void**)&p_h,     g_h);
    cudaGetSymbolAddress((void**)&p_qkv,   g_qkv);
    cudaGetSymbolAddress((void**)&p_ctx,   g_ctx);
    cudaGetSymbolAddress((void**)&p_x1,    g_x1);
    cudaGetSymbolAddress((void**)&p_a1,    g_a1);

    cudaFuncSetAttribute(gemm_mma<false,false,false,true>,
                         cudaFuncAttributeMaxDynamicSharedMemorySize, SMEM_G);
    cudaFuncSetAttribute(gemm_mma<false,true,true,false>,
                         cudaFuncAttributeMaxDynamicSharedMemorySize, SMEM_G);
    cudaFuncSetAttribute(gemm_mma<true,true,false,true>,
                         cudaFuncAttributeMaxDynamicSharedMemorySize, SMEM_G);
    cudaFuncSetAttribute(attn_tc,
                         cudaFuncAttributeMaxDynamicSharedMemorySize, ATT_SMEM);

    // 1. fused prep: LN1 + all weight transposes (one launch)
    prep_kernel<<<PREP_BLOCKS, 256>>>(x, g1, bt1, p_h,
                                      Wq, Wk, Wv, p_wqkvT,
                                      Wo, p_woT, W1, p_w1T, W2, p_w2T);
    // 2. qkv = h @ Wqkv  (fp16 out)
    gemm_mma<false,false,false,true><<<dim3(E3/BN, BT/BM), 128, SMEM_G>>>(
        p_h, p_wqkvT, nullptr, nullptr, p_qkv, BT, E3, Ee);
    // 3. ctx = causal attention (fp16 tensor core)
    attn_tc<<<dim3(Tt/64, Hh, Bb), 128, ATT_SMEM>>>(p_qkv, p_ctx);
    // 4. x1 = x + ctx @ Wo + bo  (fp32 out)
    gemm_mma<false,true,true,false><<<dim3(Ee/BN, BT/BM), 128, SMEM_G>>>(
        p_ctx, p_woT, bo, x, p_x1, BT, Ee, Ee);
    // 5. h2 = LN(x1)  (fp16)
    ln_kernel<<<BT, 256>>>(p_x1, g2, bt2, p_h);
    // 6. a1 = relu(h2 @ W1 + b1)  (fp16 out)
    gemm_mma<true,true,false,true><<<dim3(Ff/BN, BT/BM), 128, SMEM_G>>>(
        p_h, p_w1T, b1, nullptr, p_a1, BT, Ff, Ee);
    // 7. out = x1 + a1 @ W2 + b2  (fp32 out)
    gemm_mma<false,true,true,false><<<dim3(Ee/BN, BT/BM), 128, SMEM_G>>>(
        p_a1, p_w2T, b2, p_x1, out, BT, Ee, Ff);
}